// round 1
// baseline (speedup 1.0000x reference)
#include <cuda_runtime.h>

#define BATCH 16
#define NA 65536
#define NG 32
#define BLOCKS_PER_IMG (NA / 256)

// ---------------- scratch (device globals; no allocation) ----------------
__device__ unsigned long long g_gt_best[BATCH * NG];   // packed (iou_bits<<32)|~anchor
__device__ float         g_best_iou[BATCH * NA];
__device__ unsigned char g_best_idx[BATCH * NA];
__device__ float         g_neg[BATCH * NA];
__device__ unsigned int  g_hist[BATCH * 256];
__device__ int           g_np[BATCH];
__device__ float         g_loc[BATCH];
__device__ float         g_pos[BATCH];
__device__ float         g_conf[BATCH];

// ---------------- K0: zero per-launch state ----------------
__global__ void k_init() {
    int i = threadIdx.x;
    for (int j = i; j < BATCH * NG; j += blockDim.x) g_gt_best[j] = 0ull;
    for (int j = i; j < BATCH * 256; j += blockDim.x) g_hist[j] = 0u;
    if (i < BATCH) { g_np[i] = 0; g_loc[i] = 0.f; g_pos[i] = 0.f; }
}

// ---------------- K1: IoU, per-anchor best, per-gt best ----------------
__global__ __launch_bounds__(256) void k_iou(const float4* __restrict__ anchors,
                                             const float4* __restrict__ gt) {
    __shared__ float4 sgt[NG];
    __shared__ float  sarea[NG];
    __shared__ unsigned long long spart[8][NG];

    int tid = threadIdx.x;
    int b = blockIdx.x >> 8;                       // 256 blocks per image
    int a = ((blockIdx.x & 255) << 8) + tid;

    if (tid < NG) {
        float4 g = gt[b * NG + tid];
        sgt[tid] = g;
        sarea[tid] = (g.z - g.x) * (g.w - g.y);
    }
    __syncthreads();

    float4 an = anchors[b * NA + a];
    float area_a = (an.z - an.x) * (an.w - an.y);

    float best = -1.f;
    int bg = 0;
    int lane = tid & 31, wid = tid >> 5;

#pragma unroll 8
    for (int g = 0; g < NG; g++) {
        float4 gb = sgt[g];
        float lx = fmaxf(an.x, gb.x), ly = fmaxf(an.y, gb.y);
        float rx = fminf(an.z, gb.z), ry = fminf(an.w, gb.w);
        float w = fmaxf(rx - lx, 0.f), h = fmaxf(ry - ly, 0.f);
        float inter = w * h;
        float denom = area_a + sarea[g] - inter;
        float iou = __fdiv_rn(inter, denom);       // IEEE div: matches jax bitwise

        if (iou > best) { best = iou; bg = g; }    // first max wins (== argmax)

        // per-gt warp argmax; ties -> lowest lane == lowest anchor index
        unsigned bits = __float_as_uint(iou);      // iou >= 0 -> monotone bits
        unsigned m = __reduce_max_sync(0xffffffffu, bits);
        unsigned ball = __ballot_sync(0xffffffffu, bits == m);
        int src = __ffs(ball) - 1;
        if (lane == src)
            spart[wid][g] = ((unsigned long long)m << 32) | (unsigned)(~a);
    }
    __syncthreads();

    int idx = b * NA + a;
    g_best_iou[idx] = best;
    g_best_idx[idx] = (unsigned char)bg;

    if (tid < NG) {
        unsigned long long m = spart[0][tid];
#pragma unroll
        for (int w = 1; w < 8; w++) {
            unsigned long long v = spart[w][tid];
            if (v > m) m = v;                      // ~a packing: ties -> lowest anchor
        }
        atomicMax(&g_gt_best[b * NG + tid], m);
    }
}

// ---------------- K3: per-anchor loss terms + neg buffer + top-byte hist ----------------
__device__ __forceinline__ float sl1(float x) {
    float ax = fabsf(x);
    return ax < 1.f ? 0.5f * ax * ax : ax - 0.5f;
}

__global__ __launch_bounds__(256) void k_loss(const float4* __restrict__ bbox,
                                              const float* __restrict__ conf,
                                              const float4* __restrict__ gt) {
    __shared__ float4 sgt[NG];
    __shared__ unsigned int sforce[NG];
    __shared__ unsigned int shist[256];

    int tid = threadIdx.x;
    int b = blockIdx.x >> 8;
    int a = ((blockIdx.x & 255) << 8) + tid;

    shist[tid] = 0;
    if (tid < NG) {
        sgt[tid] = gt[b * NG + tid];
        sforce[tid] = ~(unsigned)(g_gt_best[b * NG + tid] & 0xFFFFFFFFull);
    }
    __syncthreads();

    int idx = b * NA + a;
    float iou = g_best_iou[idx];
    int gi = g_best_idx[idx];

    bool pos = iou > 0.5f;
#pragma unroll
    for (int g = 0; g < NG; g++) pos = pos || (sforce[g] == (unsigned)a);

    float p = conf[idx];
    float bce = pos ? -logf(p) : -log1pf(-p);
    float negv = pos ? 0.f : bce;                  // positives contribute 0 (< any neg bce)
    g_neg[idx] = negv;
    atomicAdd(&shist[__float_as_uint(negv) >> 24], 1u);

    if (pos) {
        float4 bp = bbox[idx];
        float4 m = sgt[gi];
        float d0 = (bp.x + bp.z) * 0.5f - (m.x + m.z) * 0.5f;
        float d1 = (bp.y + bp.w) * 0.5f - (m.y + m.w) * 0.5f;
        float d2 = (bp.z - bp.x) - (m.z - m.x);
        float d3 = (bp.w - bp.y) - (m.w - m.y);
        float loc = sl1(d0) + sl1(d1) + sl1(d2) + sl1(d3);
        atomicAdd(&g_np[b], 1);
        atomicAdd(&g_loc[b], loc);
        atomicAdd(&g_pos[b], bce);
    }
    __syncthreads();
    atomicAdd(&g_hist[b * 256 + tid], shist[tid]);
}

// ---------------- K4: exact top-k sum via 4-level radix select ----------------
__device__ double blockReduceD(double v, double* sred) {
    __syncthreads();                                // protect sred reuse
#pragma unroll
    for (int o = 16; o; o >>= 1) v += __shfl_down_sync(0xffffffffu, v, o);
    int w = threadIdx.x >> 5, l = threadIdx.x & 31;
    if (l == 0) sred[w] = v;
    __syncthreads();
    if (threadIdx.x < 32) {
        v = sred[threadIdx.x];
#pragma unroll
        for (int o = 16; o; o >>= 1) v += __shfl_down_sync(0xffffffffu, v, o);
    }
    return v;                                       // valid on tid 0
}

// descending byte select: find bin where cumulative-from-top crosses kk
__device__ void selectByte(unsigned* sh, unsigned* sscan,
                           unsigned* s_sel, unsigned* s_kk, unsigned* s_excl) {
    int tid = threadIdx.x;
    if (tid < 256) sscan[tid] = sh[tid];
    __syncthreads();
    for (int off = 1; off < 256; off <<= 1) {       // suffix-inclusive sum
        unsigned add = 0;
        if (tid < 256 && tid + off < 256) add = sscan[tid + off];
        __syncthreads();
        if (tid < 256) sscan[tid] += add;
        __syncthreads();
    }
    unsigned kk = *s_kk;
    if (tid < 256) {
        unsigned incl = sscan[tid];
        unsigned excl = (tid < 255) ? sscan[tid + 1] : 0u;
        if (excl < kk && kk <= incl) { *s_sel = (unsigned)tid; *s_excl = excl; }
    }
    __syncthreads();
    if (tid == 0) *s_kk = kk - *s_excl;
    __syncthreads();
}

__global__ __launch_bounds__(1024) void k_select() {
    __shared__ unsigned sh[256], sscan[256];
    __shared__ double sbinsum[256];
    __shared__ double sred[32];
    __shared__ unsigned s_sel, s_kk, s_excl, s_pref;

    int b = blockIdx.x;
    int tid = threadIdx.x;
    int np = g_np[b];
    int k = min(np * 3, NA - np);
    float posn = g_pos[b] / (float)max(np, 1);
    if (k <= 0) { if (tid == 0) g_conf[b] = posn; return; }

    const float* neg = g_neg + b * NA;

    // pass 1: top byte from prebuilt histogram
    if (tid < 256) sh[tid] = g_hist[b * 256 + tid];
    if (tid == 0) { s_kk = (unsigned)k; s_pref = 0; }
    __syncthreads();
    selectByte(sh, sscan, &s_sel, &s_kk, &s_excl);
    if (tid == 0) s_pref = s_sel;
    __syncthreads();

    // pass 2: byte 1
    if (tid < 256) sh[tid] = 0;
    __syncthreads();
    unsigned pref = s_pref;
    for (int i = tid; i < NA; i += 1024) {
        unsigned bits = __float_as_uint(neg[i]);
        if ((bits >> 24) == pref) atomicAdd(&sh[(bits >> 16) & 255], 1u);
    }
    __syncthreads();
    selectByte(sh, sscan, &s_sel, &s_kk, &s_excl);
    if (tid == 0) s_pref = (s_pref << 8) | s_sel;
    __syncthreads();

    // pass 3: byte 2
    if (tid < 256) sh[tid] = 0;
    __syncthreads();
    pref = s_pref;
    for (int i = tid; i < NA; i += 1024) {
        unsigned bits = __float_as_uint(neg[i]);
        if ((bits >> 16) == pref) atomicAdd(&sh[(bits >> 8) & 255], 1u);
    }
    __syncthreads();
    selectByte(sh, sscan, &s_sel, &s_kk, &s_excl);
    if (tid == 0) s_pref = (s_pref << 8) | s_sel;
    __syncthreads();

    // pass 4: byte 3 + fused sums
    if (tid < 256) { sh[tid] = 0; sbinsum[tid] = 0.0; }
    __syncthreads();
    pref = s_pref;                                  // 24-bit class prefix
    double myhi = 0.0;
    for (int i = tid; i < NA; i += 1024) {
        unsigned bits = __float_as_uint(neg[i]);
        unsigned hi = bits >> 8;
        if (hi == pref) {
            atomicAdd(&sh[bits & 255], 1u);
            atomicAdd(&sbinsum[bits & 255], (double)__uint_as_float(bits));
        } else if (hi > pref) {
            myhi += (double)__uint_as_float(bits);  // strictly above class
        }
    }
    __syncthreads();
    selectByte(sh, sscan, &s_sel, &s_kk, &s_excl);  // s_kk now = #ties of T to take

    double tail = (tid < 256 && tid > (int)s_sel) ? sbinsum[tid] : 0.0;
    double sumhi = blockReduceD(myhi, sred);
    double tailsum = blockReduceD(tail, sred);

    if (tid == 0) {
        unsigned r = s_kk;                          // k - count(values > T)
        float T = __uint_as_float((pref << 8) | s_sel);
        double negloss = sumhi + tailsum + (double)r * (double)T;
        g_conf[b] = posn + (float)(negloss / (double)k);
    }
}

// ---------------- K5: final combine ----------------
__global__ void k_final(float* out) {
    int tid = threadIdx.x;
    float loc = tid < BATCH ? g_loc[tid] : 0.f;
    float cf  = tid < BATCH ? g_conf[tid] : 0.f;
    int   np  = tid < BATCH ? g_np[tid] : 0;
#pragma unroll
    for (int o = 16; o; o >>= 1) {
        loc += __shfl_down_sync(0xffffffffu, loc, o);
        cf  += __shfl_down_sync(0xffffffffu, cf, o);
        np  += __shfl_down_sync(0xffffffffu, np, o);
    }
    if (tid == 0)
        out[0] = loc / (float)max(np, 1) + cf / (float)BATCH;
}

// ---------------- entry ----------------
extern "C" void kernel_launch(void* const* d_in, const int* in_sizes, int n_in,
                              void* d_out, int out_size) {
    const float4* bbox    = (const float4*)d_in[0];
    const float*  conf    = (const float*)d_in[1];
    const float4* anchors = (const float4*)d_in[2];
    const float4* gt      = (const float4*)d_in[3];

    k_init<<<1, 1024>>>();
    k_iou<<<BATCH * BLOCKS_PER_IMG, 256>>>(anchors, gt);
    k_loss<<<BATCH * BLOCKS_PER_IMG, 256>>>(bbox, conf, gt);
    k_select<<<BATCH, 1024>>>();
    k_final<<<1, 32>>>((float*)d_out);
}

// round 2
// speedup vs baseline: 1.7192x; 1.7192x over previous
#include <cuda_runtime.h>

#define B 16
#define NA 65536
#define NG 32
#define IOU_BLKS 64      // per image: 64 blocks x 1024 anchors
#define LOSS_BLKS 4      // per image: 4 blocks x 16384 anchors
#define CAP 16384

// ---------------- scratch (device globals; no allocation) ----------------
__device__ unsigned long long g_spart[B * IOU_BLKS * NG];   // per-block per-gt packed max
__device__ unsigned char g_packed[B * NA];                  // bit7 = iou>0.5, bits0-4 = best gt idx
__device__ float g_neg[B * NA];
__device__ unsigned int g_cnt[B * LOSS_BLKS * 2048];        // per-block 11-bit histograms
__device__ float        g_sum[B * LOSS_BLKS * 2048];        // per-block per-bin value sums
__device__ int   g_np[B * LOSS_BLKS];
__device__ float g_loc[B * LOSS_BLKS];
__device__ float g_pos[B * LOSS_BLKS];
__device__ float g_conf[B];

// ---------------- K1: IoU, per-anchor best gt, per-gt best anchor ----------------
__global__ __launch_bounds__(256) void k_iou(const float4* __restrict__ anchors,
                                             const float4* __restrict__ gt) {
    __shared__ float4 sgt[NG];
    __shared__ float sarea[NG];
    __shared__ unsigned long long sp[8][NG];

    int tid = threadIdx.x, lane = tid & 31, wid = tid >> 5;
    int b = blockIdx.x >> 6, blk = blockIdx.x & 63;
    int abase = blk * 1024 + tid * 4;

    if (tid < NG) {
        float4 g = gt[b * NG + tid];
        sgt[tid] = g;
        sarea[tid] = (g.z - g.x) * (g.w - g.y);
    }
    __syncthreads();

    float4 an[4]; float ar[4], best[4]; int bg[4];
    const float4* ap = anchors + b * NA + abase;
#pragma unroll
    for (int j = 0; j < 4; j++) {
        an[j] = ap[j];
        ar[j] = (an[j].z - an[j].x) * (an[j].w - an[j].y);
        best[j] = -1.f; bg[j] = 0;
    }

#pragma unroll 1
    for (int g = 0; g < NG; g++) {
        float4 gb = sgt[g];
        float sa = sarea[g];
        float gmax = -1.f; int gidx = 0;
#pragma unroll
        for (int j = 0; j < 4; j++) {
            float lx = fmaxf(an[j].x, gb.x), ly = fmaxf(an[j].y, gb.y);
            float rx = fminf(an[j].z, gb.z), ry = fminf(an[j].w, gb.w);
            float w = fmaxf(rx - lx, 0.f), h = fmaxf(ry - ly, 0.f);
            float inter = w * h;
            float q = __fdividef(inter, (ar[j] + sa) - inter);
            if (q > best[j]) { best[j] = q; bg[j] = g; }   // first max = lowest g
            if (q > gmax) { gmax = q; gidx = j; }          // first max = lowest anchor
        }
        // per-gt warp argmax: ties -> lowest lane == lowest anchor
        unsigned bits = __float_as_uint(gmax);             // q >= 0 -> monotone bits
        unsigned m = __reduce_max_sync(0xffffffffu, bits);
        unsigned ball = __ballot_sync(0xffffffffu, bits == m);
        if (lane == (__ffs(ball) - 1))
            sp[wid][g] = ((unsigned long long)m << 32) | (unsigned)(~(abase + gidx));
    }
    __syncthreads();

    uchar4 pc;
    pc.x = (unsigned char)(bg[0] | (best[0] > 0.5f ? 0x80 : 0));
    pc.y = (unsigned char)(bg[1] | (best[1] > 0.5f ? 0x80 : 0));
    pc.z = (unsigned char)(bg[2] | (best[2] > 0.5f ? 0x80 : 0));
    pc.w = (unsigned char)(bg[3] | (best[3] > 0.5f ? 0x80 : 0));
    ((uchar4*)g_packed)[(b * NA + abase) >> 2] = pc;

    if (tid < NG) {
        unsigned long long m = sp[0][tid];
#pragma unroll
        for (int w = 1; w < 8; w++) { unsigned long long v = sp[w][tid]; if (v > m) m = v; }
        g_spart[(b * IOU_BLKS + blk) * NG + tid] = m;   // plain store, no init needed
    }
}

// ---------------- K2: per-anchor loss + neg buffer + 11-bit hist/sums ----------------
__device__ __forceinline__ float sl1(float x) {
    float ax = fabsf(x);
    return ax < 1.f ? 0.5f * ax * ax : ax - 0.5f;
}

__global__ __launch_bounds__(1024) void k_loss(const float4* __restrict__ bbox,
                                               const float* __restrict__ conf,
                                               const float4* __restrict__ gt) {
    __shared__ unsigned int shist[2048];
    __shared__ float ssum[2048];
    __shared__ float4 sgt[NG];
    __shared__ unsigned int sbm[512];      // 16384-anchor bitmap of forced positives
    __shared__ int s_np;
    __shared__ float s_loc, s_pos;

    int tid = threadIdx.x;
    int b = blockIdx.x >> 2, blk = blockIdx.x & 3;
    int ablock = blk * 16384;

    shist[tid] = 0; shist[tid + 1024] = 0;
    ssum[tid] = 0.f; ssum[tid + 1024] = 0.f;
    if (tid < 512) sbm[tid] = 0;
    if (tid < NG) sgt[tid] = gt[b * NG + tid];
    if (tid == 0) { s_np = 0; s_loc = 0.f; s_pos = 0.f; }
    __syncthreads();

    // reduce per-gt forced anchors across the image's 64 iou-blocks
    if (tid < NG) {
        unsigned long long m = 0;
        for (int k = 0; k < IOU_BLKS; k++) {
            unsigned long long v = g_spart[(b * IOU_BLKS + k) * NG + tid];
            if (v > m) m = v;
        }
        int af = (int)(~(unsigned)(m & 0xffffffffu));
        int la = af - ablock;
        if (la >= 0 && la < 16384)
            atomicOr(&sbm[la >> 5], 1u << (la & 31));
    }
    __syncthreads();

    int npl = 0; float locl = 0.f, posl = 0.f;
#pragma unroll 1
    for (int i = 0; i < 16; i++) {
        int la = tid + i * 1024;
        int idx = b * NA + ablock + la;
        unsigned pk = g_packed[idx];
        bool pos = (pk & 0x80u) || ((sbm[la >> 5] >> (la & 31)) & 1u);
        float p = conf[idx];
        float negv;
        if (pos) {
            negv = 0.f;                     // < any real neg bce (>= 0.01)
            posl += -__logf(p);
            float4 bp = bbox[idx];
            float4 m = sgt[pk & 31];
            float d0 = (bp.x + bp.z) * 0.5f - (m.x + m.z) * 0.5f;
            float d1 = (bp.y + bp.w) * 0.5f - (m.y + m.w) * 0.5f;
            float d2 = (bp.z - bp.x) - (m.z - m.x);
            float d3 = (bp.w - bp.y) - (m.w - m.y);
            locl += sl1(d0) + sl1(d1) + sl1(d2) + sl1(d3);
            npl++;
        } else {
            negv = -__logf(1.0f - p);
        }
        g_neg[idx] = negv;
        unsigned key = __float_as_uint(negv) >> 21;
        atomicAdd(&shist[key], 1u);
        atomicAdd(&ssum[key], negv);
    }
    if (npl | (__float_as_uint(posl) != 0)) {
        atomicAdd(&s_np, npl); atomicAdd(&s_loc, locl); atomicAdd(&s_pos, posl);
    }
    __syncthreads();

    int base = (b * LOSS_BLKS + blk) * 2048;
    g_cnt[base + tid] = shist[tid];
    g_cnt[base + tid + 1024] = shist[tid + 1024];
    g_sum[base + tid] = ssum[tid];
    g_sum[base + tid + 1024] = ssum[tid + 1024];
    if (tid == 0) {
        g_np[b * 4 + blk] = s_np; g_loc[b * 4 + blk] = s_loc; g_pos[b * 4 + blk] = s_pos;
    }
}

// ---------------- K3: exact top-k sum: bin select + compact + smem radix ----------------
__device__ double blockReduceD(double v, double* sred) {
    __syncthreads();
#pragma unroll
    for (int o = 16; o; o >>= 1) v += __shfl_down_sync(0xffffffffu, v, o);
    int w = threadIdx.x >> 5, l = threadIdx.x & 31;
    if (l == 0) sred[w] = v;
    __syncthreads();
    if (threadIdx.x < 32) {
        v = sred[threadIdx.x];
#pragma unroll
        for (int o = 16; o; o >>= 1) v += __shfl_down_sync(0xffffffffu, v, o);
    }
    return v;   // valid on tid 0
}

extern __shared__ float dbuf[];   // 2*CAP floats (ping-pong)

__global__ __launch_bounds__(1024) void k_select() {
    __shared__ unsigned int scnt[2048];
    __shared__ float sfs[2048];
    __shared__ unsigned int h128[128];
    __shared__ float s128[128];
    __shared__ int s_n, s_sel;
    __shared__ unsigned s_kk;
    __shared__ double sred[32];
    __shared__ double s_acc;

    int b = blockIdx.x, tid = threadIdx.x;

    // combine per-block hist/sums
    unsigned c0 = 0, c1 = 0; float f0 = 0.f, f1 = 0.f;
    for (int kb = 0; kb < LOSS_BLKS; kb++) {
        int base = (b * LOSS_BLKS + kb) * 2048;
        c0 += g_cnt[base + tid];        c1 += g_cnt[base + tid + 1024];
        f0 += g_sum[base + tid];        f1 += g_sum[base + tid + 1024];
    }
    scnt[tid] = c0; scnt[tid + 1024] = c1;
    sfs[tid] = f0;  sfs[tid + 1024] = f1;

    int np = g_np[b * 4] + g_np[b * 4 + 1] + g_np[b * 4 + 2] + g_np[b * 4 + 3];
    float posn = (g_pos[b * 4] + g_pos[b * 4 + 1] + g_pos[b * 4 + 2] + g_pos[b * 4 + 3])
                 / (float)max(np, 1);
    int kn = min(3 * np, NA - np);
    if (kn <= 0) { if (tid == 0) g_conf[b] = posn; return; }
    __syncthreads();

    // suffix-inclusive scan of counts over 2048 bins
    for (int off = 1; off < 2048; off <<= 1) {
        unsigned a0 = (tid + off < 2048) ? scnt[tid + off] : 0u;
        unsigned a1 = (tid + 1024 + off < 2048) ? scnt[tid + 1024 + off] : 0u;
        __syncthreads();
        scnt[tid] += a0; scnt[tid + 1024] += a1;
        __syncthreads();
    }
    // find boundary bin
    {
        unsigned kk0 = (unsigned)kn;
        int i0 = tid, i1 = tid + 1024;
        unsigned incl0 = scnt[i0], excl0 = scnt[i0 + 1];              // i0+1 <= 2047? i0 max 1023 ok
        if (excl0 < kk0 && kk0 <= incl0) { s_sel = i0; s_kk = kk0 - excl0; }
        unsigned incl1 = scnt[i1], excl1 = (i1 < 2047) ? scnt[i1 + 1] : 0u;
        if (excl1 < kk0 && kk0 <= incl1) { s_sel = i1; s_kk = kk0 - excl1; }
    }
    __syncthreads();
    int sel = s_sel;
    unsigned kk = s_kk;

    // sum of fully-included bins (> sel)
    double av = 0.0;
    if (tid > sel) av += (double)sfs[tid];
    if (tid + 1024 > sel) av += (double)sfs[tid + 1024];
    double r = blockReduceD(av, sred);
    if (tid == 0) { s_acc = r; s_n = 0; }
    __syncthreads();

    // one pass: compact boundary-bin candidates to smem
    const float4* neg4 = (const float4*)(g_neg + b * NA);
    unsigned pref = (unsigned)sel;
    for (int i = tid; i < NA / 4; i += 1024) {
        float4 v = neg4[i];
        unsigned bx = __float_as_uint(v.x), by = __float_as_uint(v.y);
        unsigned bz = __float_as_uint(v.z), bw = __float_as_uint(v.w);
        if ((bx >> 21) == pref) { int p = atomicAdd(&s_n, 1); if (p < CAP) dbuf[p] = v.x; }
        if ((by >> 21) == pref) { int p = atomicAdd(&s_n, 1); if (p < CAP) dbuf[p] = v.y; }
        if ((bz >> 21) == pref) { int p = atomicAdd(&s_n, 1); if (p < CAP) dbuf[p] = v.z; }
        if ((bw >> 21) == pref) { int p = atomicAdd(&s_n, 1); if (p < CAP) dbuf[p] = v.w; }
    }
    __syncthreads();
    int n = s_n;
    bool ovf = (n > CAP);
    float* cur = dbuf;
    float* nxt = dbuf + CAP;
    int curn = n;

    // 3 radix levels over remaining 21 bits (7 bits each)
#pragma unroll 1
    for (int shift = 14; shift >= 0; shift -= 7) {
        if (tid < 128) { h128[tid] = 0u; s128[tid] = 0.f; }
        __syncthreads();
        if (!ovf) {
            for (int i = tid; i < curn; i += 1024) {
                float v = cur[i];
                unsigned key = (__float_as_uint(v) >> shift) & 127u;
                atomicAdd(&h128[key], 1u);
                atomicAdd(&s128[key], v);
            }
        } else {
            // fallback: rescan global with prefix match
            for (int i = tid; i < NA / 4; i += 1024) {
                float4 v = neg4[i];
                float vv[4] = {v.x, v.y, v.z, v.w};
#pragma unroll
                for (int c = 0; c < 4; c++) {
                    unsigned bits = __float_as_uint(vv[c]);
                    if ((bits >> (shift + 7)) == pref) {
                        unsigned key = (bits >> shift) & 127u;
                        atomicAdd(&h128[key], 1u);
                        atomicAdd(&s128[key], vv[c]);
                    }
                }
            }
        }
        __syncthreads();
        // suffix scan over 128 bins
        for (int off = 1; off < 128; off <<= 1) {
            unsigned a = 0;
            if (tid < 128 && tid + off < 128) a = h128[tid + off];
            __syncthreads();
            if (tid < 128) h128[tid] += a;
            __syncthreads();
        }
        if (tid < 128) {
            unsigned incl = h128[tid], excl = (tid < 127) ? h128[tid + 1] : 0u;
            if (excl < kk && kk <= incl) { s_sel = tid; s_kk = kk - excl; }
        }
        __syncthreads();
        int sel2 = s_sel;
        kk = s_kk;
        double av2 = (tid < 128 && tid > sel2) ? (double)s128[tid] : 0.0;
        double r2 = blockReduceD(av2, sred);
        if (tid == 0) s_acc += r2;

        if (shift > 0 && !ovf) {
            if (tid == 0) s_n = 0;
            __syncthreads();
            for (int i = tid; i < curn; i += 1024) {
                float v = cur[i];
                if (((__float_as_uint(v) >> shift) & 127u) == (unsigned)sel2)
                    nxt[atomicAdd(&s_n, 1)] = v;
            }
            __syncthreads();
            curn = s_n;
            float* t = cur; cur = nxt; nxt = t;
        }
        pref = (pref << 7) | (unsigned)sel2;
        __syncthreads();
    }

    if (tid == 0) {
        double acc = s_acc + (double)kk * (double)__uint_as_float(pref);
        g_conf[b] = posn + (float)(acc / (double)kn);
    }
}

// ---------------- K4: final combine ----------------
__global__ void k_final(float* out) {
    int tid = threadIdx.x;  // 32 threads
    float loc = g_loc[tid] + g_loc[tid + 32];
    int   np  = g_np[tid]  + g_np[tid + 32];
    float cf  = tid < B ? g_conf[tid] : 0.f;
#pragma unroll
    for (int o = 16; o; o >>= 1) {
        loc += __shfl_down_sync(0xffffffffu, loc, o);
        np  += __shfl_down_sync(0xffffffffu, np, o);
        cf  += __shfl_down_sync(0xffffffffu, cf, o);
    }
    if (tid == 0)
        out[0] = loc / (float)max(np, 1) + cf / (float)B;
}

// ---------------- entry ----------------
extern "C" void kernel_launch(void* const* d_in, const int* in_sizes, int n_in,
                              void* d_out, int out_size) {
    const float4* bbox    = (const float4*)d_in[0];
    const float*  conf    = (const float*)d_in[1];
    const float4* anchors = (const float4*)d_in[2];
    const float4* gt      = (const float4*)d_in[3];

    cudaFuncSetAttribute(k_select, cudaFuncAttributeMaxDynamicSharedMemorySize,
                         2 * CAP * (int)sizeof(float));

    k_iou<<<B * IOU_BLKS, 256>>>(anchors, gt);
    k_loss<<<B * LOSS_BLKS, 1024>>>(bbox, conf, gt);
    k_select<<<B, 1024, 2 * CAP * sizeof(float)>>>();
    k_final<<<1, 32>>>((float*)d_out);
}

// round 3
// speedup vs baseline: 1.9417x; 1.1294x over previous
#include <cuda_runtime.h>

#define B 16
#define NA 65536
#define NG 32
#define IOU_BLKS 64      // per image: 64 blocks x 256 threads x 4 anchors
#define CAP 16384

// ---------------- scratch (device globals; zero at module load) ----------------
__device__ unsigned long long g_spart[B * IOU_BLKS * NG];  // per-block per-gt packed max
__device__ float        g_neg[B * NA];
__device__ unsigned int g_hcnt[B * 2048];   // K1 atomics; K2 consumes then re-zeroes
__device__ int   g_np[B];                   // idem
__device__ float g_loc[B];
__device__ float g_pos[B];
__device__ float g_cf[B];                   // per-image results (plain stores)
__device__ float g_locf[B];
__device__ int   g_npf[B];
__device__ unsigned int g_done;             // ticket; last block resets to 0

__device__ __forceinline__ float sl1(float x) {
    float ax = fabsf(x);
    return ax < 1.f ? 0.5f * ax * ax : ax - 0.5f;
}

// ---------------- K1: IoU + per-anchor loss (pos0 = iou>0.5) + count hist ----------------
__global__ __launch_bounds__(256) void k_main(const float4* __restrict__ bbox,
                                              const float* __restrict__ conf,
                                              const float4* __restrict__ anchors,
                                              const float4* __restrict__ gt) {
    __shared__ float4 sgt[NG];
    __shared__ float sarea[NG];
    __shared__ unsigned long long sp[8][NG];
    __shared__ unsigned int shist[2048];
    __shared__ int s_np; __shared__ float s_loc, s_pos;

    int tid = threadIdx.x, lane = tid & 31, wid = tid >> 5;
    int b = blockIdx.x >> 6, blk = blockIdx.x & 63;
    int abase = blk * 1024 + tid * 4;

    for (int i = tid; i < 2048; i += 256) shist[i] = 0;
    if (tid < NG) {
        float4 g = gt[b * NG + tid];
        sgt[tid] = g;
        sarea[tid] = (g.z - g.x) * (g.w - g.y);
    }
    if (tid == 0) { s_np = 0; s_loc = 0.f; s_pos = 0.f; }
    __syncthreads();

    float4 an[4]; float ar[4], best[4]; int bg[4];
    const float4* ap = anchors + b * NA + abase;
#pragma unroll
    for (int j = 0; j < 4; j++) {
        an[j] = ap[j];
        ar[j] = (an[j].z - an[j].x) * (an[j].w - an[j].y);
        best[j] = -1.f; bg[j] = 0;
    }

#pragma unroll 1
    for (int g = 0; g < NG; g++) {
        float4 gb = sgt[g];
        float sa = sarea[g];
        float gmax = -1.f; int gidx = 0;
#pragma unroll
        for (int j = 0; j < 4; j++) {
            float lx = fmaxf(an[j].x, gb.x), ly = fmaxf(an[j].y, gb.y);
            float rx = fminf(an[j].z, gb.z), ry = fminf(an[j].w, gb.w);
            float w = fmaxf(rx - lx, 0.f), h = fmaxf(ry - ly, 0.f);
            float inter = w * h;
            float q = __fdividef(inter, (ar[j] + sa) - inter);
            if (q > best[j]) { best[j] = q; bg[j] = g; }   // first max = lowest g
            if (q > gmax) { gmax = q; gidx = j; }          // first max = lowest anchor
        }
        // per-gt warp argmax: ties -> lowest lane == lowest anchor
        unsigned bits = __float_as_uint(gmax);
        unsigned m = __reduce_max_sync(0xffffffffu, bits);
        unsigned ball = __ballot_sync(0xffffffffu, bits == m);
        if (lane == (__ffs(ball) - 1))
            sp[wid][g] = ((unsigned long long)m << 32) | (unsigned)(~(abase + gidx));
    }

    float4 cf4 = *(const float4*)(conf + b * NA + abase);
    float pv[4] = {cf4.x, cf4.y, cf4.z, cf4.w};
    float ng[4];
    int npl = 0; float locl = 0.f, posl = 0.f;
#pragma unroll
    for (int j = 0; j < 4; j++) {
        if (best[j] > 0.5f) {
            ng[j] = 0.f;
            posl += -__logf(pv[j]);
            float4 bp = bbox[b * NA + abase + j];
            float4 m = sgt[bg[j]];
            float d0 = (bp.x + bp.z) * 0.5f - (m.x + m.z) * 0.5f;
            float d1 = (bp.y + bp.w) * 0.5f - (m.y + m.w) * 0.5f;
            float d2 = (bp.z - bp.x) - (m.z - m.x);
            float d3 = (bp.w - bp.y) - (m.w - m.y);
            locl += sl1(d0) + sl1(d1) + sl1(d2) + sl1(d3);
            npl++;
        } else {
            ng[j] = fmaxf(-__logf(1.0f - pv[j]), 0.0f);    // kill any -0.0
        }
        atomicAdd(&shist[__float_as_uint(ng[j]) >> 21], 1u);
    }
    *(float4*)(g_neg + b * NA + abase) = make_float4(ng[0], ng[1], ng[2], ng[3]);
    if (npl) { atomicAdd(&s_np, npl); atomicAdd(&s_loc, locl); atomicAdd(&s_pos, posl); }
    __syncthreads();

    for (int i = tid; i < 2048; i += 256) {
        unsigned c = shist[i];
        if (c) atomicAdd(&g_hcnt[b * 2048 + i], c);        // sparse flush
    }
    if (tid < NG) {
        unsigned long long m = sp[0][tid];
#pragma unroll
        for (int w = 1; w < 8; w++) { unsigned long long v = sp[w][tid]; if (v > m) m = v; }
        g_spart[(b * IOU_BLKS + blk) * NG + tid] = m;
    }
    if (tid == 0 && s_np) {
        atomicAdd(&g_np[b], s_np);
        atomicAdd(&g_loc[b], s_loc);
        atomicAdd(&g_pos[b], s_pos);
    }
}

// ---------------- K2: forced-anchor correction + exact top-k + final ----------------
__device__ double blockReduceD(double v, double* sred) {
    __syncthreads();
#pragma unroll
    for (int o = 16; o; o >>= 1) v += __shfl_down_sync(0xffffffffu, v, o);
    int w = threadIdx.x >> 5, l = threadIdx.x & 31;
    if (l == 0) sred[w] = v;
    __syncthreads();
    if (threadIdx.x < 32) {
        v = sred[threadIdx.x];
#pragma unroll
        for (int o = 16; o; o >>= 1) v += __shfl_down_sync(0xffffffffu, v, o);
    }
    return v;   // valid on tid 0
}

extern __shared__ float dbuf[];   // 2*CAP floats

__global__ __launch_bounds__(1024) void k_sel(const float4* __restrict__ bbox,
                                              const float* __restrict__ conf,
                                              const float4* __restrict__ anchors,
                                              const float4* __restrict__ gt,
                                              float* __restrict__ out) {
    __shared__ float4 sgt[NG];
    __shared__ float sarea[NG];
    __shared__ unsigned scnt[2048];
    __shared__ unsigned h128[128];
    __shared__ int s_af[NG];
    __shared__ int s_n, s_sel;
    __shared__ unsigned s_kk;
    __shared__ double sred[32];
    __shared__ double s_acc;
    __shared__ int s_npc; __shared__ float s_locc, s_posc;
    __shared__ int s_gnp; __shared__ float s_gloc, s_gpos;

    int b = blockIdx.x, tid = threadIdx.x;

    if (tid < NG) {
        float4 g = gt[b * NG + tid];
        sgt[tid] = g;
        sarea[tid] = (g.z - g.x) * (g.w - g.y);
    }
    if (tid == 0) {
        s_npc = 0; s_locc = 0.f; s_posc = 0.f; s_acc = 0.0; s_n = 0; s_sel = 0; s_kk = 0;
        s_gnp = g_np[b]; s_gloc = g_loc[b]; s_gpos = g_pos[b];
        g_np[b] = 0; g_loc[b] = 0.f; g_pos[b] = 0.f;       // clean for next replay
    }
    // hist: load to smem, zero global for next replay
    scnt[tid]        = g_hcnt[b * 2048 + tid];
    scnt[tid + 1024] = g_hcnt[b * 2048 + tid + 1024];
    g_hcnt[b * 2048 + tid] = 0;
    g_hcnt[b * 2048 + tid + 1024] = 0;

    // reduce forced-anchor partials
    if (tid < NG) {
        unsigned long long m = 0;
        const unsigned long long* spp = g_spart + (size_t)b * IOU_BLKS * NG + tid;
        for (int k2 = 0; k2 < IOU_BLKS; k2++) {
            unsigned long long v = spp[k2 * NG];
            if (v > m) m = v;
        }
        s_af[tid] = (int)(~(unsigned)(m & 0xffffffffull));
    }
    __syncthreads();

    // corrections: forced anchors not already pos0
    if (tid < NG) {
        int af = s_af[tid];
        bool apply = true;
        for (int g2 = 0; g2 < tid; g2++) if (s_af[g2] == af) apply = false;   // dedupe
        if (apply) {
            float4 an = anchors[b * NA + af];
            float area_a = (an.z - an.x) * (an.w - an.y);
            float bestv = -1.f; int bgi = 0;
#pragma unroll 1
            for (int g = 0; g < NG; g++) {                 // bitwise-identical to K1
                float4 gb = sgt[g];
                float lx = fmaxf(an.x, gb.x), ly = fmaxf(an.y, gb.y);
                float rx = fminf(an.z, gb.z), ry = fminf(an.w, gb.w);
                float w = fmaxf(rx - lx, 0.f), h = fmaxf(ry - ly, 0.f);
                float inter = w * h;
                float q = __fdividef(inter, (area_a + sarea[g]) - inter);
                if (q > bestv) { bestv = q; bgi = g; }
            }
            if (!(bestv > 0.5f)) {
                int idx = b * NA + af;
                float old = g_neg[idx];
                g_neg[idx] = 0.f;
                atomicSub(&scnt[__float_as_uint(old) >> 21], 1u);
                atomicAdd(&scnt[0], 1u);
                float p = conf[idx];
                float4 bp = bbox[idx];
                float4 m = sgt[bgi];
                float d0 = (bp.x + bp.z) * 0.5f - (m.x + m.z) * 0.5f;
                float d1 = (bp.y + bp.w) * 0.5f - (m.y + m.w) * 0.5f;
                float d2 = (bp.z - bp.x) - (m.z - m.x);
                float d3 = (bp.w - bp.y) - (m.w - m.y);
                atomicAdd(&s_npc, 1);
                atomicAdd(&s_locc, sl1(d0) + sl1(d1) + sl1(d2) + sl1(d3));
                atomicAdd(&s_posc, -__logf(p));
            }
        }
    }
    __syncthreads();

    int np = s_gnp + s_npc;
    float posn = (s_gpos + s_posc) / (float)max(np, 1);
    float locim = s_gloc + s_locc;
    int kn = min(3 * np, NA - np);
    unsigned kk0 = (unsigned)max(kn, 1);

    // suffix-inclusive scan of 2048 counts
    for (int off = 1; off < 2048; off <<= 1) {
        unsigned a0 = (tid + off < 2048) ? scnt[tid + off] : 0u;
        unsigned a1 = (tid + 1024 + off < 2048) ? scnt[tid + 1024 + off] : 0u;
        __syncthreads();
        scnt[tid] += a0; scnt[tid + 1024] += a1;
        __syncthreads();
    }
    {
        unsigned incl0 = scnt[tid], excl0 = scnt[tid + 1];
        if (excl0 < kk0 && kk0 <= incl0) { s_sel = tid; s_kk = kk0 - excl0; }
        int i1 = tid + 1024;
        unsigned incl1 = scnt[i1], excl1 = (i1 < 2047) ? scnt[i1 + 1] : 0u;
        if (excl1 < kk0 && kk0 <= incl1) { s_sel = i1; s_kk = kk0 - excl1; }
    }
    __syncthreads();
    int sel = s_sel;
    unsigned kk = s_kk;

    // single scan: double sum of bins > sel, compact bin == sel
    const float4* neg4 = (const float4*)(g_neg + b * NA);
    double dsum = 0.0;
    for (int i = tid; i < NA / 4; i += 1024) {
        float4 v = neg4[i];
        float vv[4] = {v.x, v.y, v.z, v.w};
#pragma unroll
        for (int c = 0; c < 4; c++) {
            int key = (int)(__float_as_uint(vv[c]) >> 21);
            if (key > sel) dsum += (double)vv[c];
            else if (key == sel) { int p = atomicAdd(&s_n, 1); if (p < CAP) dbuf[p] = vv[c]; }
        }
    }
    double r = blockReduceD(dsum, sred);
    if (tid == 0) s_acc += r;
    __syncthreads();

    int count_sel = s_n;
    bool ovf = count_sel > CAP;
    float* cur = dbuf; float* nxt = dbuf + CAP;
    int curn = ovf ? 0 : count_sel;
    unsigned pref = (unsigned)sel;                  // 11 bits so far

#pragma unroll 1
    for (int shift = 14; shift >= 0; shift -= 7) {
        if (!ovf && kk == (unsigned)curn) {         // take-all fast path (uniform)
            double dv = 0.0;
            for (int i = tid; i < curn; i += 1024) dv += (double)cur[i];
            double rr = blockReduceD(dv, sred);
            if (tid == 0) s_acc += rr;
            kk = 0;
            break;
        }
        if (tid < 128) h128[tid] = 0u;
        __syncthreads();
        if (!ovf) {
            for (int i = tid; i < curn; i += 1024)
                atomicAdd(&h128[(__float_as_uint(cur[i]) >> shift) & 127u], 1u);
        } else {
            for (int i = tid; i < NA / 4; i += 1024) {
                float4 v = neg4[i];
                float vv[4] = {v.x, v.y, v.z, v.w};
#pragma unroll
                for (int c = 0; c < 4; c++) {
                    unsigned bits = __float_as_uint(vv[c]);
                    if ((bits >> (shift + 7)) == pref)
                        atomicAdd(&h128[(bits >> shift) & 127u], 1u);
                }
            }
        }
        __syncthreads();
        for (int off = 1; off < 128; off <<= 1) {
            unsigned a = 0;
            if (tid < 128 && tid + off < 128) a = h128[tid + off];
            __syncthreads();
            if (tid < 128) h128[tid] += a;
            __syncthreads();
        }
        if (tid < 128) {
            unsigned incl = h128[tid], excl = (tid < 127) ? h128[tid + 1] : 0u;
            if (excl < kk && kk <= incl) { s_sel = tid; s_kk = kk - excl; }
        }
        if (tid == 0) s_n = 0;
        __syncthreads();
        int sel2 = s_sel;
        int nextcnt = (int)(h128[sel2] - ((sel2 < 127) ? h128[sel2 + 1] : 0u));
        bool fits = nextcnt <= CAP;

        double dv = 0.0;
        if (!ovf) {
            for (int i = tid; i < curn; i += 1024) {
                float v2 = cur[i];
                int key = (int)((__float_as_uint(v2) >> shift) & 127u);
                if (key > sel2) dv += (double)v2;
                else if (key == sel2 && shift > 0) nxt[atomicAdd(&s_n, 1)] = v2;
            }
        } else {
            for (int i = tid; i < NA / 4; i += 1024) {
                float4 v = neg4[i];
                float vv[4] = {v.x, v.y, v.z, v.w};
#pragma unroll
                for (int c = 0; c < 4; c++) {
                    unsigned bits = __float_as_uint(vv[c]);
                    if ((bits >> (shift + 7)) == pref) {
                        int key = (int)((bits >> shift) & 127u);
                        if (key > sel2) dv += (double)vv[c];
                        else if (key == sel2 && shift > 0 && fits)
                            cur[atomicAdd(&s_n, 1)] = vv[c];   // compact into dbuf
                    }
                }
            }
        }
        double rr = blockReduceD(dv, sred);
        if (tid == 0) s_acc += rr;
        __syncthreads();

        kk = s_kk;
        if (!ovf) {
            curn = s_n;
            float* t = cur; cur = nxt; nxt = t;
        } else if (fits) {
            ovf = false;
            curn = s_n;                              // cur == dbuf already
        }
        pref = (pref << 7) | (unsigned)sel2;
        __syncthreads();
    }

    if (tid == 0) {
        double negloss = s_acc + (double)kk * (double)__uint_as_float(pref);
        g_cf[b]   = posn + (float)(negloss / (double)max(kn, 1));
        g_locf[b] = locim;
        g_npf[b]  = np;
        __threadfence();
        unsigned t = atomicAdd(&g_done, 1u);
        if (t == B - 1) {
            g_done = 0;                              // clean for next replay
            __threadfence();
            float cs = 0.f, ls = 0.f; int ns = 0;
#pragma unroll
            for (int i = 0; i < B; i++) {
                cs += __ldcg(&g_cf[i]);              // bypass stale L1
                ls += __ldcg(&g_locf[i]);
                ns += __ldcg(&g_npf[i]);
            }
            out[0] = ls / (float)max(ns, 1) + cs / (float)B;
        }
    }
}

// ---------------- entry ----------------
extern "C" void kernel_launch(void* const* d_in, const int* in_sizes, int n_in,
                              void* d_out, int out_size) {
    const float4* bbox    = (const float4*)d_in[0];
    const float*  conf    = (const float*)d_in[1];
    const float4* anchors = (const float4*)d_in[2];
    const float4* gt      = (const float4*)d_in[3];

    cudaFuncSetAttribute(k_sel, cudaFuncAttributeMaxDynamicSharedMemorySize,
                         2 * CAP * (int)sizeof(float));

    k_main<<<B * IOU_BLKS, 256>>>(bbox, conf, anchors, gt);
    k_sel<<<B, 1024, 2 * CAP * sizeof(float)>>>(bbox, conf, anchors, gt, (float*)d_out);
}

// round 4
// speedup vs baseline: 2.5468x; 1.3117x over previous
#include <cuda_runtime.h>

#define B 16
#define NA 65536
#define NG 32
#define IOU_BLKS 64      // per image: 64 blocks x 256 threads x 4 anchors
#define CAP 16384

// ---------------- scratch (device globals; zero at module load) ----------------
__device__ unsigned long long g_spart[B * IOU_BLKS * NG];  // per-block per-gt packed max
__device__ float        g_neg[B * NA];
__device__ unsigned int g_hcnt[B * 2048];   // K1 atomics; K2 consumes then re-zeroes
__device__ int   g_np[B];
__device__ float g_loc[B];
__device__ float g_pos[B];
__device__ float g_cf[B];
__device__ float g_locf[B];
__device__ int   g_npf[B];
__device__ unsigned int g_done;

__device__ __forceinline__ float sl1(float x) {
    float ax = fabsf(x);
    return ax < 1.f ? 0.5f * ax * ax : ax - 0.5f;
}

// ---------------- K1: IoU + per-anchor loss (pos0 = iou>0.5) + count hist ----------------
__global__ __launch_bounds__(256) void k_main(const float4* __restrict__ bbox,
                                              const float* __restrict__ conf,
                                              const float4* __restrict__ anchors,
                                              const float4* __restrict__ gt) {
    __shared__ float4 sgt[NG];
    __shared__ float sarea[NG];
    __shared__ unsigned long long sp[8][NG];
    __shared__ unsigned int shist[2048];
    __shared__ int s_np; __shared__ float s_loc, s_pos;

    int tid = threadIdx.x, lane = tid & 31, wid = tid >> 5;
    int b = blockIdx.x >> 6, blk = blockIdx.x & 63;
    int abase = blk * 1024 + tid * 4;

    for (int i = tid; i < 2048; i += 256) shist[i] = 0;
    if (tid < NG) {
        float4 g = gt[b * NG + tid];
        sgt[tid] = g;
        sarea[tid] = (g.z - g.x) * (g.w - g.y);
    }
    if (tid == 0) { s_np = 0; s_loc = 0.f; s_pos = 0.f; }
    __syncthreads();

    float4 an[4]; float ar[4], best[4]; int bg[4];
    const float4* ap = anchors + b * NA + abase;
#pragma unroll
    for (int j = 0; j < 4; j++) {
        an[j] = ap[j];
        ar[j] = (an[j].z - an[j].x) * (an[j].w - an[j].y);
        best[j] = -1.f; bg[j] = 0;
    }

#pragma unroll 1
    for (int g = 0; g < NG; g++) {
        float4 gb = sgt[g];
        float sa = sarea[g];
        float gmax = -1.f; int gidx = 0;
#pragma unroll
        for (int j = 0; j < 4; j++) {
            float lx = fmaxf(an[j].x, gb.x), ly = fmaxf(an[j].y, gb.y);
            float rx = fminf(an[j].z, gb.z), ry = fminf(an[j].w, gb.w);
            float w = fmaxf(rx - lx, 0.f), h = fmaxf(ry - ly, 0.f);
            float inter = w * h;
            float q = __fdividef(inter, (ar[j] + sa) - inter);
            if (q > best[j]) { best[j] = q; bg[j] = g; }   // first max = lowest g
            if (q > gmax) { gmax = q; gidx = j; }          // first max = lowest anchor
        }
        unsigned bits = __float_as_uint(gmax);
        unsigned m = __reduce_max_sync(0xffffffffu, bits);
        unsigned ball = __ballot_sync(0xffffffffu, bits == m);
        if (lane == (__ffs(ball) - 1))
            sp[wid][g] = ((unsigned long long)m << 32) | (unsigned)(~(abase + gidx));
    }

    float4 cf4 = *(const float4*)(conf + b * NA + abase);
    float pv[4] = {cf4.x, cf4.y, cf4.z, cf4.w};
    float ng[4];
    int npl = 0; float locl = 0.f, posl = 0.f;
#pragma unroll
    for (int j = 0; j < 4; j++) {
        if (best[j] > 0.5f) {
            ng[j] = 0.f;
            posl += -__logf(pv[j]);
            float4 bp = bbox[b * NA + abase + j];
            float4 m = sgt[bg[j]];
            float d0 = (bp.x + bp.z) * 0.5f - (m.x + m.z) * 0.5f;
            float d1 = (bp.y + bp.w) * 0.5f - (m.y + m.w) * 0.5f;
            float d2 = (bp.z - bp.x) - (m.z - m.x);
            float d3 = (bp.w - bp.y) - (m.w - m.y);
            locl += sl1(d0) + sl1(d1) + sl1(d2) + sl1(d3);
            npl++;
        } else {
            ng[j] = fmaxf(-__logf(1.0f - pv[j]), 0.0f);
        }
        atomicAdd(&shist[__float_as_uint(ng[j]) >> 21], 1u);
    }
    *(float4*)(g_neg + b * NA + abase) = make_float4(ng[0], ng[1], ng[2], ng[3]);
    if (npl) { atomicAdd(&s_np, npl); atomicAdd(&s_loc, locl); atomicAdd(&s_pos, posl); }
    __syncthreads();

    for (int i = tid; i < 2048; i += 256) {
        unsigned c = shist[i];
        if (c) atomicAdd(&g_hcnt[b * 2048 + i], c);
    }
    if (tid < NG) {
        unsigned long long m = sp[0][tid];
#pragma unroll
        for (int w = 1; w < 8; w++) { unsigned long long v = sp[w][tid]; if (v > m) m = v; }
        g_spart[(b * IOU_BLKS + blk) * NG + tid] = m;
    }
    if (tid == 0 && s_np) {
        atomicAdd(&g_np[b], s_np);
        atomicAdd(&g_loc[b], s_loc);
        atomicAdd(&g_pos[b], s_pos);
    }
}

// ---------------- K2: corrections + exact top-k + final ----------------
__device__ double blockReduceD(double v, double* sred) {
    __syncthreads();
#pragma unroll
    for (int o = 16; o; o >>= 1) v += __shfl_down_sync(0xffffffffu, v, o);
    int w = threadIdx.x >> 5, l = threadIdx.x & 31;
    if (l == 0) sred[w] = v;
    __syncthreads();
    if (threadIdx.x < 32) {
        v = sred[threadIdx.x];
#pragma unroll
        for (int o = 16; o; o >>= 1) v += __shfl_down_sync(0xffffffffu, v, o);
    }
    return v;   // valid on tid 0
}

extern __shared__ float dbuf[];   // 2*CAP floats

__global__ __launch_bounds__(1024) void k_sel(const float4* __restrict__ bbox,
                                              const float* __restrict__ conf,
                                              const float4* __restrict__ anchors,
                                              const float4* __restrict__ gt,
                                              float* __restrict__ out) {
    __shared__ float4 sgt[NG];
    __shared__ float sarea[NG];
    __shared__ unsigned scnt[2048];
    __shared__ unsigned long long s_gmax[NG];
    __shared__ int s_af[NG];
    __shared__ unsigned h128[128];
    __shared__ float s128f[128];
    __shared__ int s_n, s_sel;
    __shared__ unsigned s_kk;
    __shared__ double sred[32];
    __shared__ double s_acc;
    __shared__ int s_npc; __shared__ float s_locc, s_posc;
    __shared__ int s_gnp; __shared__ float s_gloc, s_gpos;

    int b = blockIdx.x, tid = threadIdx.x;
    int lane = tid & 31, wrp = tid >> 5;

    if (tid < NG) {
        float4 g = gt[b * NG + tid];
        sgt[tid] = g;
        sarea[tid] = (g.z - g.x) * (g.w - g.y);
        s_gmax[tid] = 0ull;
    }
    if (tid == 0) {
        s_npc = 0; s_locc = 0.f; s_posc = 0.f; s_acc = 0.0; s_n = 0; s_sel = 0; s_kk = 0;
        s_gnp = g_np[b]; s_gloc = g_loc[b]; s_gpos = g_pos[b];
        g_np[b] = 0; g_loc[b] = 0.f; g_pos[b] = 0.f;
    }
    scnt[tid]        = g_hcnt[b * 2048 + tid];
    scnt[tid + 1024] = g_hcnt[b * 2048 + tid + 1024];
    g_hcnt[b * 2048 + tid] = 0;
    g_hcnt[b * 2048 + tid + 1024] = 0;
    __syncthreads();

    // parallel reduce of forced-anchor partials: 2048 u64, coalesced
    {
        unsigned long long v0 = g_spart[(size_t)b * 2048 + tid];
        unsigned long long v1 = g_spart[(size_t)b * 2048 + tid + 1024];
        atomicMax(&s_gmax[tid & 31], v0);
        atomicMax(&s_gmax[(tid + 1024) & 31], v1);
    }
    __syncthreads();
    if (tid < NG) s_af[tid] = (int)(~(unsigned)(s_gmax[tid] & 0xffffffffull));
    __syncthreads();

    // corrections: warp w handles forced anchor of gt w; lanes = 32 gts in parallel
    {
        int af = s_af[wrp];
        unsigned dup = __ballot_sync(0xffffffffu, lane < wrp && s_af[lane] == af);
        if (dup == 0) {
            float4 an = anchors[b * NA + af];
            float area_a = (an.z - an.x) * (an.w - an.y);
            float4 gb = sgt[lane];
            float lx = fmaxf(an.x, gb.x), ly = fmaxf(an.y, gb.y);
            float rx = fminf(an.z, gb.z), ry = fminf(an.w, gb.w);
            float w = fmaxf(rx - lx, 0.f), h = fmaxf(ry - ly, 0.f);
            float inter = w * h;
            float q = __fdividef(inter, (area_a + sarea[lane]) - inter);  // bit-identical to K1
            unsigned bits = __float_as_uint(q);
            unsigned m = __reduce_max_sync(0xffffffffu, bits);
            unsigned ball = __ballot_sync(0xffffffffu, bits == m);
            int bgi = __ffs(ball) - 1;                    // lowest gt index on ties
            float bestq = __uint_as_float(m);
            if (!(bestq > 0.5f) && lane == 0) {
                int idx = b * NA + af;
                float old = g_neg[idx];
                g_neg[idx] = 0.f;
                atomicSub(&scnt[__float_as_uint(old) >> 21], 1u);
                atomicAdd(&scnt[0], 1u);
                float p = conf[idx];
                float4 bp = bbox[idx];
                float4 mg = sgt[bgi];
                float d0 = (bp.x + bp.z) * 0.5f - (mg.x + mg.z) * 0.5f;
                float d1 = (bp.y + bp.w) * 0.5f - (mg.y + mg.w) * 0.5f;
                float d2 = (bp.z - bp.x) - (mg.z - mg.x);
                float d3 = (bp.w - bp.y) - (mg.w - mg.y);
                atomicAdd(&s_npc, 1);
                atomicAdd(&s_locc, sl1(d0) + sl1(d1) + sl1(d2) + sl1(d3));
                atomicAdd(&s_posc, -__logf(p));
            }
        }
    }
    __syncthreads();

    int np = s_gnp + s_npc;
    float posn = (s_gpos + s_posc) / (float)max(np, 1);
    float locim = s_gloc + s_locc;
    int kn = min(3 * np, NA - np);
    unsigned kk0 = (unsigned)max(kn, 1);

    // suffix-inclusive scan of 2048 counts
    for (int off = 1; off < 2048; off <<= 1) {
        unsigned a0 = (tid + off < 2048) ? scnt[tid + off] : 0u;
        unsigned a1 = (tid + 1024 + off < 2048) ? scnt[tid + 1024 + off] : 0u;
        __syncthreads();
        scnt[tid] += a0; scnt[tid + 1024] += a1;
        __syncthreads();
    }
    {
        unsigned incl0 = scnt[tid], excl0 = scnt[tid + 1];
        if (excl0 < kk0 && kk0 <= incl0) { s_sel = tid; s_kk = kk0 - excl0; }
        int i1 = tid + 1024;
        unsigned incl1 = scnt[i1], excl1 = (i1 < 2047) ? scnt[i1 + 1] : 0u;
        if (excl1 < kk0 && kk0 <= incl1) { s_sel = i1; s_kk = kk0 - excl1; }
    }
    __syncthreads();
    int sel = s_sel;
    unsigned kk = s_kk;

    // single scan: Kahan-float sum of bins > sel, compact bin == sel (NO fp64 per element)
    const float4* neg4 = (const float4*)(g_neg + b * NA);
    float ks = 0.f, kc = 0.f;
    for (int i = tid; i < NA / 4; i += 1024) {
        float4 v = neg4[i];
        float vv[4] = {v.x, v.y, v.z, v.w};
#pragma unroll
        for (int c = 0; c < 4; c++) {
            int key = (int)(__float_as_uint(vv[c]) >> 21);
            if (key > sel) {
                float y = vv[c] - kc;
                float t = ks + y;
                kc = (t - ks) - y;
                ks = t;
            } else if (key == sel) {
                int p = atomicAdd(&s_n, 1);
                if (p < CAP) dbuf[p] = vv[c];
            }
        }
    }
    double r = blockReduceD((double)ks - (double)kc, sred);
    if (tid == 0) s_acc += r;
    __syncthreads();

    int count_sel = s_n;
    bool ovf = count_sel > CAP;
    float* cur = dbuf; float* nxt = dbuf + CAP;
    int curn = ovf ? 0 : count_sel;
    unsigned pref = (unsigned)sel;

#pragma unroll 1
    for (int shift = 14; shift >= 0; shift -= 7) {
        if (!ovf && kk == (unsigned)curn) {          // take-all fast path
            float as = 0.f, ac = 0.f;
            for (int i = tid; i < curn; i += 1024) {
                float y = cur[i] - ac;
                float t = as + y;
                ac = (t - as) - y;
                as = t;
            }
            double rr = blockReduceD((double)as - (double)ac, sred);
            if (tid == 0) s_acc += rr;
            kk = 0;
            break;
        }
        if (tid < 128) { h128[tid] = 0u; s128f[tid] = 0.f; }
        __syncthreads();
        if (!ovf) {
            for (int i = tid; i < curn; i += 1024) {
                float v = cur[i];
                unsigned key = (__float_as_uint(v) >> shift) & 127u;
                atomicAdd(&h128[key], 1u);
                atomicAdd(&s128f[key], v);
            }
        } else {
            for (int i = tid; i < NA / 4; i += 1024) {
                float4 v = neg4[i];
                float vv[4] = {v.x, v.y, v.z, v.w};
#pragma unroll
                for (int c = 0; c < 4; c++) {
                    unsigned bits = __float_as_uint(vv[c]);
                    if ((bits >> (shift + 7)) == pref) {
                        atomicAdd(&h128[(bits >> shift) & 127u], 1u);
                        atomicAdd(&s128f[(bits >> shift) & 127u], vv[c]);
                    }
                }
            }
        }
        __syncthreads();
        for (int off = 1; off < 128; off <<= 1) {
            unsigned a = 0;
            if (tid < 128 && tid + off < 128) a = h128[tid + off];
            __syncthreads();
            if (tid < 128) h128[tid] += a;
            __syncthreads();
        }
        if (tid < 128) {
            unsigned incl = h128[tid], excl = (tid < 127) ? h128[tid + 1] : 0u;
            if (excl < kk && kk <= incl) { s_sel = tid; s_kk = kk - excl; }
        }
        if (tid == 0) s_n = 0;
        __syncthreads();
        int sel2 = s_sel;
        int nextcnt = (int)(h128[sel2] - ((sel2 < 127) ? h128[sel2 + 1] : 0u));
        bool fits = nextcnt <= CAP;

        // sum of fully-included sub-bins from the per-bin float sums (128 values only)
        double dv = (tid < 128 && tid > sel2) ? (double)s128f[tid] : 0.0;
        double rr = blockReduceD(dv, sred);
        if (tid == 0) s_acc += rr;
        __syncthreads();

        if (shift > 0) {
            if (!ovf) {
                for (int i = tid; i < curn; i += 1024) {
                    float v2 = cur[i];
                    if (((__float_as_uint(v2) >> shift) & 127u) == (unsigned)sel2)
                        nxt[atomicAdd(&s_n, 1)] = v2;
                }
            } else if (fits) {
                for (int i = tid; i < NA / 4; i += 1024) {
                    float4 v = neg4[i];
                    float vv[4] = {v.x, v.y, v.z, v.w};
#pragma unroll
                    for (int c = 0; c < 4; c++) {
                        unsigned bits = __float_as_uint(vv[c]);
                        if ((bits >> (shift + 7)) == pref &&
                            ((bits >> shift) & 127u) == (unsigned)sel2)
                            cur[atomicAdd(&s_n, 1)] = vv[c];
                    }
                }
            }
            __syncthreads();
            kk = s_kk;
            if (!ovf) {
                curn = s_n;
                float* t = cur; cur = nxt; nxt = t;
            } else if (fits) {
                ovf = false;
                curn = s_n;
            }
        } else {
            kk = s_kk;
        }
        pref = (pref << 7) | (unsigned)sel2;
        __syncthreads();
    }

    if (tid == 0) {
        double negloss = s_acc + (double)kk * (double)__uint_as_float(pref);
        g_cf[b]   = posn + (float)(negloss / (double)max(kn, 1));
        g_locf[b] = locim;
        g_npf[b]  = np;
        __threadfence();
        unsigned t = atomicAdd(&g_done, 1u);
        if (t == B - 1) {
            g_done = 0;
            __threadfence();
            float cs = 0.f, ls = 0.f; int ns = 0;
#pragma unroll
            for (int i = 0; i < B; i++) {
                cs += __ldcg(&g_cf[i]);
                ls += __ldcg(&g_locf[i]);
                ns += __ldcg(&g_npf[i]);
            }
            out[0] = ls / (float)max(ns, 1) + cs / (float)B;
        }
    }
}

// ---------------- entry ----------------
extern "C" void kernel_launch(void* const* d_in, const int* in_sizes, int n_in,
                              void* d_out, int out_size) {
    const float4* bbox    = (const float4*)d_in[0];
    const float*  conf    = (const float*)d_in[1];
    const float4* anchors = (const float4*)d_in[2];
    const float4* gt      = (const float4*)d_in[3];

    cudaFuncSetAttribute(k_sel, cudaFuncAttributeMaxDynamicSharedMemorySize,
                         2 * CAP * (int)sizeof(float));

    k_main<<<B * IOU_BLKS, 256>>>(bbox, conf, anchors, gt);
    k_sel<<<B, 1024, 2 * CAP * sizeof(float)>>>(bbox, conf, anchors, gt, (float*)d_out);
}